// round 1
// baseline (speedup 1.0000x reference)
#include <cuda_runtime.h>
#include <cuda_bf16.h>
#include <math.h>

// Problem constants
#define B_   2
#define S_   2048
#define H_   4096
#define NH_  32
#define NKV_ 2
#define HD_  128
#define ROT_ 64
#define QKV_N 4608            // (NH + 2*NKV) * HD
#define TOKS (B_ * S_)        // 4096

// Scratch (device globals; no allocation allowed)
__device__ float g_qkv[(size_t)TOKS * QKV_N];   // ~75.5 MB
__device__ float g_attn[(size_t)TOKS * H_];     // ~67 MB

// ---------------------------------------------------------------------------
// SGEMM: C[M,N] = A[M,K] @ B[K,N] (+ bias). 128x128 tile, BK=8, 256 threads,
// 8x8 per-thread micro-tile, reg prefetch. M,N,K multiples of 128/8 assumed.
// ---------------------------------------------------------------------------
__global__ __launch_bounds__(256) void sgemm_kernel(
    const float* __restrict__ A, const float* __restrict__ Bm,
    const float* __restrict__ bias, float* __restrict__ C,
    int M, int N, int K, int hasBias)
{
    __shared__ float As[8][132];
    __shared__ float Bs[8][132];

    const int tid = threadIdx.x;
    const int tx = tid & 15;       // 0..15 -> N direction
    const int ty = tid >> 4;       // 0..15 -> M direction
    const int m0 = blockIdx.y * 128;
    const int n0 = blockIdx.x * 128;

    // A tile loader mapping: 128 rows x 8 cols, one float4 per thread
    const int arow = tid >> 1;          // 0..127
    const int acol = (tid & 1) * 4;     // 0 or 4
    // B tile loader mapping: 8 rows x 128 cols, one float4 per thread
    const int brow = tid >> 5;          // 0..7
    const int bcol = (tid & 31) * 4;    // 0..124

    const float* Aptr = A + (size_t)(m0 + arow) * K + acol;
    const float* Bptr = Bm + (size_t)brow * N + n0 + bcol;

    float acc[8][8];
#pragma unroll
    for (int i = 0; i < 8; i++)
#pragma unroll
        for (int j = 0; j < 8; j++) acc[i][j] = 0.f;

    float4 a4 = *(const float4*)(Aptr);
    float4 b4 = *(const float4*)(Bptr);

    for (int kt = 0; kt < K; kt += 8) {
        // store current tile to shared
        As[acol + 0][arow] = a4.x;
        As[acol + 1][arow] = a4.y;
        As[acol + 2][arow] = a4.z;
        As[acol + 3][arow] = a4.w;
        *(float4*)&Bs[brow][bcol] = b4;
        __syncthreads();

        // prefetch next tile into registers
        if (kt + 8 < K) {
            a4 = *(const float4*)(Aptr + (kt + 8));
            b4 = *(const float4*)(Bptr + (size_t)(kt + 8) * N);
        }

#pragma unroll
        for (int kk = 0; kk < 8; kk++) {
            float4 af0 = *(float4*)&As[kk][ty * 8];
            float4 af1 = *(float4*)&As[kk][ty * 8 + 4];
            float4 bf0 = *(float4*)&Bs[kk][tx * 8];
            float4 bf1 = *(float4*)&Bs[kk][tx * 8 + 4];
            float av[8] = {af0.x, af0.y, af0.z, af0.w, af1.x, af1.y, af1.z, af1.w};
            float bv[8] = {bf0.x, bf0.y, bf0.z, bf0.w, bf1.x, bf1.y, bf1.z, bf1.w};
#pragma unroll
            for (int i = 0; i < 8; i++)
#pragma unroll
                for (int j = 0; j < 8; j++)
                    acc[i][j] += av[i] * bv[j];
        }
        __syncthreads();
    }

    // epilogue
#pragma unroll
    for (int i = 0; i < 8; i++) {
        size_t row = (size_t)(m0 + ty * 8 + i);
        float* crow = C + row * N + n0 + tx * 8;
        if (hasBias) {
            const float* bp = bias + n0 + tx * 8;
#pragma unroll
            for (int j = 0; j < 8; j++) crow[j] = acc[i][j] + bp[j];
        } else {
#pragma unroll
            for (int j = 0; j < 8; j++) crow[j] = acc[i][j];
        }
    }
}

// ---------------------------------------------------------------------------
// GLM partial RoPE applied in-place to q (heads 0..31) and k (heads 32..33)
// within the qkv buffer. One thread per (token, head, pair).
// rot pair i: dims (2i, 2i+1) of first ROT dims, angle = pos * 10000^(-2i/ROT)
// ---------------------------------------------------------------------------
__global__ void rope_kernel(float* __restrict__ qkv, const int* __restrict__ positions)
{
    int idx = blockIdx.x * blockDim.x + threadIdx.x;
    const int total = TOKS * (NH_ + NKV_) * (ROT_ / 2);
    if (idx >= total) return;
    int i = idx & 31;                   // pair 0..31
    int head = (idx >> 5) % (NH_ + NKV_);
    int tok = idx / ((NH_ + NKV_) * 32);
    int pos = positions[tok];

    double freq = exp(-((double)(2 * i) / (double)ROT_) * log(10000.0));
    double ang = (double)pos * freq;
    float c = (float)cos(ang);
    float s = (float)sin(ang);

    int off = (head < NH_) ? head * HD_ : (NH_ * HD_ + (head - NH_) * HD_);
    float* p = qkv + (size_t)tok * QKV_N + off + 2 * i;
    float x1 = p[0], x2 = p[1];
    p[0] = x1 * c - x2 * s;
    p[1] = x1 * s + x2 * c;
}

// ---------------------------------------------------------------------------
// Causal GQA flash attention, fp32.
// Grid: (S/64 q-tiles, NH, B). Block: 256 threads.
// Thread (r = tid>>2, q = tid&3): owns q-row r, score cols q*16..q*16+15,
// output dims q*32..q*32+31. Online softmax state replicated across quad.
// ---------------------------------------------------------------------------
#define ATT_BM 64
#define ATT_BN 64
#define QK_PAD 132
#define PS_PAD 65

__global__ __launch_bounds__(256) void attn_kernel(
    const float* __restrict__ qkv, float* __restrict__ out)
{
    extern __shared__ float sm[];
    float* Qs = sm;                        // 64 x 132
    float* Ks = Qs + ATT_BM * QK_PAD;      // 64 x 132
    float* Vs = Ks + ATT_BN * QK_PAD;      // 64 x 132
    float* Ps = Vs + ATT_BN * QK_PAD;      // 64 x 65

    const int qt = blockIdx.x;
    const int h  = blockIdx.y;
    const int b  = blockIdx.z;
    const int kv = h >> 4;                 // G = NH/NKV = 16
    const int tid = threadIdx.x;
    const int r = tid >> 2;
    const int q = tid & 3;
    const int q_glob = qt * ATT_BM + r;

    // load Q tile (64 rows x 128 dims)
    const float* qbase = qkv + (size_t)(b * S_ + qt * ATT_BM) * QKV_N + h * HD_;
    for (int idx = tid; idx < ATT_BM * 32; idx += 256) {
        int row = idx >> 5, c = idx & 31;
        float4 v = *(const float4*)(qbase + (size_t)row * QKV_N + c * 4);
        float* dst = &Qs[row * QK_PAD + c * 4];
        dst[0] = v.x; dst[1] = v.y; dst[2] = v.z; dst[3] = v.w;
    }

    float m_run = -1e30f, l_run = 0.f;
    float acc[32];
#pragma unroll
    for (int i = 0; i < 32; i++) acc[i] = 0.f;
    const float scale = 0.08838834764831845f;  // 1/sqrt(128)

    const float* kbase = qkv + (size_t)b * S_ * QKV_N + NH_ * HD_ + kv * HD_;
    const float* vbase = kbase + NKV_ * HD_;

    for (int t = 0; t <= qt; ++t) {
        __syncthreads();   // previous PV readers done before overwrite
        for (int idx = tid; idx < ATT_BN * 32; idx += 256) {
            int row = idx >> 5, c = idx & 31;
            size_t goff = (size_t)(t * ATT_BN + row) * QKV_N + c * 4;
            float4 k4 = *(const float4*)(kbase + goff);
            float4 v4 = *(const float4*)(vbase + goff);
            float* kd = &Ks[row * QK_PAD + c * 4];
            kd[0] = k4.x; kd[1] = k4.y; kd[2] = k4.z; kd[3] = k4.w;
            float* vd = &Vs[row * QK_PAD + c * 4];
            vd[0] = v4.x; vd[1] = v4.y; vd[2] = v4.z; vd[3] = v4.w;
        }
        __syncthreads();

        // scores for this thread's 16 key columns
        float s[16];
#pragma unroll
        for (int jj = 0; jj < 16; jj++) s[jj] = 0.f;
        for (int kk = 0; kk < HD_; kk += 4) {
            float4 qv = *(float4*)&Qs[r * QK_PAD + kk];
#pragma unroll
            for (int jj = 0; jj < 16; jj++) {
                float4 k4 = *(float4*)&Ks[(q * 16 + jj) * QK_PAD + kk];
                s[jj] += qv.x * k4.x + qv.y * k4.y + qv.z * k4.z + qv.w * k4.w;
            }
        }
        const int jg0 = t * ATT_BN + q * 16;
#pragma unroll
        for (int jj = 0; jj < 16; jj++)
            s[jj] = (jg0 + jj <= q_glob) ? s[jj] * scale : -1e30f;

        float mt = s[0];
#pragma unroll
        for (int jj = 1; jj < 16; jj++) mt = fmaxf(mt, s[jj]);
        mt = fmaxf(mt, __shfl_xor_sync(0xffffffffu, mt, 1));
        mt = fmaxf(mt, __shfl_xor_sync(0xffffffffu, mt, 2));
        float m_new = fmaxf(m_run, mt);

        float lt = 0.f;
#pragma unroll
        for (int jj = 0; jj < 16; jj++) {
            float p = __expf(s[jj] - m_new);
            Ps[r * PS_PAD + q * 16 + jj] = p;
            lt += p;
        }
        lt += __shfl_xor_sync(0xffffffffu, lt, 1);
        lt += __shfl_xor_sync(0xffffffffu, lt, 2);

        float alpha = __expf(m_run - m_new);
        l_run = l_run * alpha + lt;
        m_run = m_new;
#pragma unroll
        for (int i = 0; i < 32; i++) acc[i] *= alpha;

        __syncwarp();   // Ps exchange is intra-warp (quads of a row share a warp)

        // PV: acc[d] += sum_j Ps[r][j] * Vs[j][q*32 + d]
#pragma unroll 4
        for (int j = 0; j < ATT_BN; j++) {
            float pv = Ps[r * PS_PAD + j];
            const float* vrow = &Vs[j * QK_PAD + q * 32];
#pragma unroll
            for (int d4 = 0; d4 < 8; d4++) {
                float4 vv = *(const float4*)(vrow + d4 * 4);
                acc[d4 * 4 + 0] += pv * vv.x;
                acc[d4 * 4 + 1] += pv * vv.y;
                acc[d4 * 4 + 2] += pv * vv.z;
                acc[d4 * 4 + 3] += pv * vv.w;
            }
        }
    }

    float inv_l = 1.f / l_run;
    float* orow = out + (size_t)(b * S_ + q_glob) * H_ + h * HD_ + q * 32;
#pragma unroll
    for (int d4 = 0; d4 < 8; d4++) {
        float4 ov;
        ov.x = acc[d4 * 4 + 0] * inv_l;
        ov.y = acc[d4 * 4 + 1] * inv_l;
        ov.z = acc[d4 * 4 + 2] * inv_l;
        ov.w = acc[d4 * 4 + 3] * inv_l;
        *(float4*)(orow + d4 * 4) = ov;
    }
}

// ---------------------------------------------------------------------------
extern "C" void kernel_launch(void* const* d_in, const int* in_sizes, int n_in,
                              void* d_out, int out_size)
{
    const float* hidden   = (const float*)d_in[0];
    const float* w_qkv    = (const float*)d_in[1];
    const float* b_qkv    = (const float*)d_in[2];
    const float* w_dense  = (const float*)d_in[3];
    const int*   positions = (const int*)d_in[4];
    float* out = (float*)d_out;

    float* qkv_buf = nullptr;
    float* attn_buf = nullptr;
    cudaGetSymbolAddress((void**)&qkv_buf, g_qkv);
    cudaGetSymbolAddress((void**)&attn_buf, g_attn);

    // 1) QKV GEMM + bias: [4096,4096] @ [4096,4608]
    sgemm_kernel<<<dim3(QKV_N / 128, TOKS / 128), 256>>>(
        hidden, w_qkv, b_qkv, qkv_buf, TOKS, QKV_N, H_, 1);

    // 2) RoPE in place on q + k heads
    {
        int total = TOKS * (NH_ + NKV_) * (ROT_ / 2);
        rope_kernel<<<(total + 255) / 256, 256>>>(qkv_buf, positions);
    }

    // 3) causal GQA flash attention
    {
        size_t smem = (size_t)(3 * ATT_BM * QK_PAD + ATT_BM * PS_PAD) * sizeof(float);
        cudaFuncSetAttribute(attn_kernel, cudaFuncAttributeMaxDynamicSharedMemorySize, (int)smem);
        attn_kernel<<<dim3(S_ / ATT_BM, NH_, B_), 256, smem>>>(qkv_buf, attn_buf);
    }

    // 4) dense GEMM: [4096,4096] @ [4096,4096]
    sgemm_kernel<<<dim3(H_ / 128, TOKS / 128), 256>>>(
        attn_buf, w_dense, nullptr, out, TOKS, H_, H_, 0);
}

// round 6
// speedup vs baseline: 1.2324x; 1.2324x over previous
#include <cuda_runtime.h>
#include <cuda_bf16.h>
#include <cstdint>
#include <math.h>

// Problem constants
#define B_   2
#define S_   2048
#define H_   4096
#define NH_  32
#define NKV_ 2
#define HD_  128
#define ROT_ 64
#define QKV_N 4608            // (NH + 2*NKV) * HD
#define TOKS (B_ * S_)        // 4096

// Scratch (device globals; no allocation allowed)
__device__ float g_qkv[(size_t)TOKS * QKV_N];   // ~75.5 MB
__device__ float g_attn[(size_t)TOKS * H_];     // ~67 MB

// ---------------------------------------------------------------------------
// TF32 tensor-core GEMM: C[M,N] = A[M,K] @ B[K,N] (+ bias)
// 128x128x32 CTA tile, 256 threads = 8 warps (2x4), warp tile 64x32.
// mma.sync.aligned.m16n8k8.row.col.f32.tf32.tf32.f32
// Smem: A [128][36] (pad 4 -> bank (4g+t) conflict-free frag loads)
//       B [32][136] (pad 8 -> bank (8t+g) conflict-free frag loads)
// Register prefetch of the next K-stage overlaps LDG with mma compute.
// ---------------------------------------------------------------------------
#define BM 128
#define BN 128
#define BK 32
#define A_PAD 36
#define B_PAD 136

__device__ __forceinline__ float to_tf32(float x) {
    float y;
    asm("cvt.rna.tf32.f32 %0, %1;" : "=f"(y) : "f"(x));
    return y;
}

__device__ __forceinline__ void mma_tf32(float* d,
                                         const uint32_t* a,
                                         const uint32_t* b) {
    asm volatile(
        "mma.sync.aligned.m16n8k8.row.col.f32.tf32.tf32.f32 "
        "{%0,%1,%2,%3}, {%4,%5,%6,%7}, {%8,%9}, {%0,%1,%2,%3};\n"
        : "+f"(d[0]), "+f"(d[1]), "+f"(d[2]), "+f"(d[3])
        : "r"(a[0]), "r"(a[1]), "r"(a[2]), "r"(a[3]),
          "r"(b[0]), "r"(b[1]));
}

__global__ __launch_bounds__(256) void tf32_gemm_kernel(
    const float* __restrict__ A, const float* __restrict__ Bm,
    const float* __restrict__ bias, float* __restrict__ C,
    int M, int N, int K, int hasBias)
{
    __shared__ float As[BM][A_PAD];
    __shared__ float Bs[BK][B_PAD];

    const int tid  = threadIdx.x;
    const int warp = tid >> 5;
    const int lane = tid & 31;
    const int g = lane >> 2;          // 0..7
    const int t = lane & 3;           // 0..3
    const int wm = (warp >> 2) * 64;  // warp m offset: 0 or 64
    const int wn = (warp & 3) * 32;   // warp n offset: 0..96
    const int m_blk = blockIdx.y * BM;
    const int n_blk = blockIdx.x * BN;

    // global->reg loader mapping
    const int a_r = tid >> 3;         // base row 0..31 (stride 32 per iter)
    const int a_c = (tid & 7) * 4;    // col 0..28
    const int b_r = tid >> 5;         // base row 0..7 (stride 8 per iter)
    const int b_c = (tid & 31) * 4;   // col 0..124

    const float* Ag = A + (size_t)(m_blk + a_r) * K + a_c;
    const float* Bg = Bm + (size_t)b_r * N + n_blk + b_c;

    float acc[4][4][4];
#pragma unroll
    for (int i = 0; i < 4; i++)
#pragma unroll
        for (int j = 0; j < 4; j++)
#pragma unroll
            for (int c = 0; c < 4; c++) acc[i][j][c] = 0.f;

    float4 pa[4], pb[4];
#pragma unroll
    for (int it = 0; it < 4; it++) {
        pa[it] = *(const float4*)(Ag + (size_t)(it * 32) * K);
        pb[it] = *(const float4*)(Bg + (size_t)(it * 8) * N);
    }

    for (int kt = 0; kt < K; kt += BK) {
        // store stage to smem (with tf32 rounding)
#pragma unroll
        for (int it = 0; it < 4; it++) {
            float4 v = pa[it];
            float4 w;
            w.x = to_tf32(v.x); w.y = to_tf32(v.y);
            w.z = to_tf32(v.z); w.w = to_tf32(v.w);
            *(float4*)&As[a_r + it * 32][a_c] = w;
            v = pb[it];
            w.x = to_tf32(v.x); w.y = to_tf32(v.y);
            w.z = to_tf32(v.z); w.w = to_tf32(v.w);
            *(float4*)&Bs[b_r + it * 8][b_c] = w;
        }
        __syncthreads();

        // prefetch next stage
        if (kt + BK < K) {
#pragma unroll
            for (int it = 0; it < 4; it++) {
                pa[it] = *(const float4*)(Ag + (kt + BK) + (size_t)(it * 32) * K);
                pb[it] = *(const float4*)(Bg + (size_t)(kt + BK + it * 8) * N);
            }
        }

        // compute 4 k-steps of 8
#pragma unroll
        for (int kk = 0; kk < 4; kk++) {
            const int k0 = kk * 8;
            uint32_t af[4][4], bf[4][2];
#pragma unroll
            for (int i = 0; i < 4; i++) {
                const float* ab = &As[wm + i * 16 + g][k0 + t];
                af[i][0] = __float_as_uint(ab[0]);
                af[i][1] = __float_as_uint(ab[8 * A_PAD]);
                af[i][2] = __float_as_uint(ab[4]);
                af[i][3] = __float_as_uint(ab[8 * A_PAD + 4]);
            }
#pragma unroll
            for (int j = 0; j < 4; j++) {
                const float* bb = &Bs[k0 + t][wn + j * 8 + g];
                bf[j][0] = __float_as_uint(bb[0]);
                bf[j][1] = __float_as_uint(bb[4 * B_PAD]);
            }
#pragma unroll
            for (int i = 0; i < 4; i++)
#pragma unroll
                for (int j = 0; j < 4; j++)
                    mma_tf32(acc[i][j], af[i], bf[j]);
        }
        __syncthreads();
    }

    // epilogue: c0:(g, 2t) c1:(g, 2t+1) c2:(g+8, 2t) c3:(g+8, 2t+1)
#pragma unroll
    for (int i = 0; i < 4; i++) {
#pragma unroll
        for (int j = 0; j < 4; j++) {
            int row = m_blk + wm + i * 16 + g;
            int col = n_blk + wn + j * 8 + t * 2;
            float b0 = 0.f, b1 = 0.f;
            if (hasBias) { b0 = bias[col]; b1 = bias[col + 1]; }
            float2 v0 = make_float2(acc[i][j][0] + b0, acc[i][j][1] + b1);
            float2 v1 = make_float2(acc[i][j][2] + b0, acc[i][j][3] + b1);
            *(float2*)&C[(size_t)row * N + col] = v0;
            *(float2*)&C[(size_t)(row + 8) * N + col] = v1;
        }
    }
}

// ---------------------------------------------------------------------------
// GLM partial RoPE applied in-place to q (heads 0..31) and k (heads 32..33)
// ---------------------------------------------------------------------------
__global__ void rope_kernel(float* __restrict__ qkv, const int* __restrict__ positions)
{
    int idx = blockIdx.x * blockDim.x + threadIdx.x;
    const int total = TOKS * (NH_ + NKV_) * (ROT_ / 2);
    if (idx >= total) return;
    int i = idx & 31;                   // pair 0..31
    int head = (idx >> 5) % (NH_ + NKV_);
    int tok = idx / ((NH_ + NKV_) * 32);
    int pos = positions[tok];

    double freq = exp(-((double)(2 * i) / (double)ROT_) * log(10000.0));
    double ang = (double)pos * freq;
    float c = (float)cos(ang);
    float s = (float)sin(ang);

    int off = (head < NH_) ? head * HD_ : (NH_ * HD_ + (head - NH_) * HD_);
    float* p = qkv + (size_t)tok * QKV_N + off + 2 * i;
    float x1 = p[0], x2 = p[1];
    p[0] = x1 * c - x2 * s;
    p[1] = x1 * s + x2 * c;
}

// ---------------------------------------------------------------------------
// Causal GQA flash attention, fp32 (unchanged from R1 baseline).
// ---------------------------------------------------------------------------
#define ATT_BM 64
#define ATT_BN 64
#define QK_PAD 132
#define PS_PAD 65

__global__ __launch_bounds__(256) void attn_kernel(
    const float* __restrict__ qkv, float* __restrict__ out)
{
    extern __shared__ float sm[];
    float* Qs = sm;                        // 64 x 132
    float* Ks = Qs + ATT_BM * QK_PAD;      // 64 x 132
    float* Vs = Ks + ATT_BN * QK_PAD;      // 64 x 132
    float* Ps = Vs + ATT_BN * QK_PAD;      // 64 x 65

    const int qt = blockIdx.x;
    const int h  = blockIdx.y;
    const int b  = blockIdx.z;
    const int kv = h >> 4;                 // G = NH/NKV = 16
    const int tid = threadIdx.x;
    const int r = tid >> 2;
    const int q = tid & 3;
    const int q_glob = qt * ATT_BM + r;

    const float* qbase = qkv + (size_t)(b * S_ + qt * ATT_BM) * QKV_N + h * HD_;
    for (int idx = tid; idx < ATT_BM * 32; idx += 256) {
        int row = idx >> 5, c = idx & 31;
        float4 v = *(const float4*)(qbase + (size_t)row * QKV_N + c * 4);
        float* dst = &Qs[row * QK_PAD + c * 4];
        dst[0] = v.x; dst[1] = v.y; dst[2] = v.z; dst[3] = v.w;
    }

    float m_run = -1e30f, l_run = 0.f;
    float acc[32];
#pragma unroll
    for (int i = 0; i < 32; i++) acc[i] = 0.f;
    const float scale = 0.08838834764831845f;  // 1/sqrt(128)

    const float* kbase = qkv + (size_t)b * S_ * QKV_N + NH_ * HD_ + kv * HD_;
    const float* vbase = kbase + NKV_ * HD_;

    for (int t = 0; t <= qt; ++t) {
        __syncthreads();
        for (int idx = tid; idx < ATT_BN * 32; idx += 256) {
            int row = idx >> 5, c = idx & 31;
            size_t goff = (size_t)(t * ATT_BN + row) * QKV_N + c * 4;
            float4 k4 = *(const float4*)(kbase + goff);
            float4 v4 = *(const float4*)(vbase + goff);
            float* kd = &Ks[row * QK_PAD + c * 4];
            kd[0] = k4.x; kd[1] = k4.y; kd[2] = k4.z; kd[3] = k4.w;
            float* vd = &Vs[row * QK_PAD + c * 4];
            vd[0] = v4.x; vd[1] = v4.y; vd[2] = v4.z; vd[3] = v4.w;
        }
        __syncthreads();

        float s[16];
#pragma unroll
        for (int jj = 0; jj < 16; jj++) s[jj] = 0.f;
        for (int kk = 0; kk < HD_; kk += 4) {
            float4 qv = *(float4*)&Qs[r * QK_PAD + kk];
#pragma unroll
            for (int jj = 0; jj < 16; jj++) {
                float4 k4 = *(float4*)&Ks[(q * 16 + jj) * QK_PAD + kk];
                s[jj] += qv.x * k4.x + qv.y * k4.y + qv.z * k4.z + qv.w * k4.w;
            }
        }
        const int jg0 = t * ATT_BN + q * 16;
#pragma unroll
        for (int jj = 0; jj < 16; jj++)
            s[jj] = (jg0 + jj <= q_glob) ? s[jj] * scale : -1e30f;

        float mt = s[0];
#pragma unroll
        for (int jj = 1; jj < 16; jj++) mt = fmaxf(mt, s[jj]);
        mt = fmaxf(mt, __shfl_xor_sync(0xffffffffu, mt, 1));
        mt = fmaxf(mt, __shfl_xor_sync(0xffffffffu, mt, 2));
        float m_new = fmaxf(m_run, mt);

        float lt = 0.f;
#pragma unroll
        for (int jj = 0; jj < 16; jj++) {
            float p = __expf(s[jj] - m_new);
            Ps[r * PS_PAD + q * 16 + jj] = p;
            lt += p;
        }
        lt += __shfl_xor_sync(0xffffffffu, lt, 1);
        lt += __shfl_xor_sync(0xffffffffu, lt, 2);

        float alpha = __expf(m_run - m_new);
        l_run = l_run * alpha + lt;
        m_run = m_new;
#pragma unroll
        for (int i = 0; i < 32; i++) acc[i] *= alpha;

        __syncwarp();

#pragma unroll 4
        for (int j = 0; j < ATT_BN; j++) {
            float pv = Ps[r * PS_PAD + j];
            const float* vrow = &Vs[j * QK_PAD + q * 32];
#pragma unroll
            for (int d4 = 0; d4 < 8; d4++) {
                float4 vv = *(const float4*)(vrow + d4 * 4);
                acc[d4 * 4 + 0] += pv * vv.x;
                acc[d4 * 4 + 1] += pv * vv.y;
                acc[d4 * 4 + 2] += pv * vv.z;
                acc[d4 * 4 + 3] += pv * vv.w;
            }
        }
    }

    float inv_l = 1.f / l_run;
    float* orow = out + (size_t)(b * S_ + q_glob) * H_ + h * HD_ + q * 32;
#pragma unroll
    for (int d4 = 0; d4 < 8; d4++) {
        float4 ov;
        ov.x = acc[d4 * 4 + 0] * inv_l;
        ov.y = acc[d4 * 4 + 1] * inv_l;
        ov.z = acc[d4 * 4 + 2] * inv_l;
        ov.w = acc[d4 * 4 + 3] * inv_l;
        *(float4*)(orow + d4 * 4) = ov;
    }
}

// ---------------------------------------------------------------------------
extern "C" void kernel_launch(void* const* d_in, const int* in_sizes, int n_in,
                              void* d_out, int out_size)
{
    const float* hidden    = (const float*)d_in[0];
    const float* w_qkv     = (const float*)d_in[1];
    const float* b_qkv     = (const float*)d_in[2];
    const float* w_dense   = (const float*)d_in[3];
    const int*   positions = (const int*)d_in[4];
    float* out = (float*)d_out;

    float* qkv_buf = nullptr;
    float* attn_buf = nullptr;
    cudaGetSymbolAddress((void**)&qkv_buf, g_qkv);
    cudaGetSymbolAddress((void**)&attn_buf, g_attn);

    // 1) QKV GEMM + bias: [4096,4096] @ [4096,4608]  (tf32 tensor cores)
    tf32_gemm_kernel<<<dim3(QKV_N / BN, TOKS / BM), 256>>>(
        hidden, w_qkv, b_qkv, qkv_buf, TOKS, QKV_N, H_, 1);

    // 2) RoPE in place on q + k heads
    {
        int total = TOKS * (NH_ + NKV_) * (ROT_ / 2);
        rope_kernel<<<(total + 255) / 256, 256>>>(qkv_buf, positions);
    }

    // 3) causal GQA flash attention (fp32)
    {
        size_t smem = (size_t)(3 * ATT_BM * QK_PAD + ATT_BM * PS_PAD) * sizeof(float);
        cudaFuncSetAttribute(attn_kernel, cudaFuncAttributeMaxDynamicSharedMemorySize, (int)smem);
        attn_kernel<<<dim3(S_ / ATT_BM, NH_, B_), 256, smem>>>(qkv_buf, attn_buf);
    }

    // 4) dense GEMM: [4096,4096] @ [4096,4096]  (tf32 tensor cores)
    tf32_gemm_kernel<<<dim3(H_ / BN, TOKS / BM), 256>>>(
        attn_buf, w_dense, nullptr, out, TOKS, H_, H_, 0);
}

// round 9
// speedup vs baseline: 6.8118x; 5.5271x over previous
#include <cuda_runtime.h>
#include <cuda_bf16.h>
#include <cstdint>
#include <math.h>

// Problem constants
#define B_   2
#define S_   2048
#define H_   4096
#define NH_  32
#define NKV_ 2
#define HD_  128
#define ROT_ 64
#define QKV_N 4608            // (NH + 2*NKV) * HD
#define TOKS (B_ * S_)        // 4096

// Scratch (device globals; no allocation allowed)
__device__ float g_qkv[(size_t)TOKS * QKV_N];   // ~75.5 MB
__device__ float g_attn[(size_t)TOKS * H_];     // ~67 MB

__device__ __forceinline__ float to_tf32(float x) {
    float y;
    asm("cvt.rna.tf32.f32 %0, %1;" : "=f"(y) : "f"(x));
    return y;
}

__device__ __forceinline__ void mma_tf32(float* d,
                                         const uint32_t* a,
                                         const uint32_t* b) {
    asm volatile(
        "mma.sync.aligned.m16n8k8.row.col.f32.tf32.tf32.f32 "
        "{%0,%1,%2,%3}, {%4,%5,%6,%7}, {%8,%9}, {%0,%1,%2,%3};\n"
        : "+f"(d[0]), "+f"(d[1]), "+f"(d[2]), "+f"(d[3])
        : "r"(a[0]), "r"(a[1]), "r"(a[2]), "r"(a[3]),
          "r"(b[0]), "r"(b[1]));
}

// ---------------------------------------------------------------------------
// TF32 tensor-core GEMM (unchanged from R6): C = A @ B (+bias)
// ---------------------------------------------------------------------------
#define BM 128
#define BN 128
#define BK 32
#define A_PAD 36
#define B_PAD 136

__global__ __launch_bounds__(256) void tf32_gemm_kernel(
    const float* __restrict__ A, const float* __restrict__ Bm,
    const float* __restrict__ bias, float* __restrict__ C,
    int M, int N, int K, int hasBias)
{
    __shared__ float As[BM][A_PAD];
    __shared__ float Bs[BK][B_PAD];

    const int tid  = threadIdx.x;
    const int warp = tid >> 5;
    const int lane = tid & 31;
    const int g = lane >> 2;
    const int t = lane & 3;
    const int wm = (warp >> 2) * 64;
    const int wn = (warp & 3) * 32;
    const int m_blk = blockIdx.y * BM;
    const int n_blk = blockIdx.x * BN;

    const int a_r = tid >> 3;
    const int a_c = (tid & 7) * 4;
    const int b_r = tid >> 5;
    const int b_c = (tid & 31) * 4;

    const float* Ag = A + (size_t)(m_blk + a_r) * K + a_c;
    const float* Bg = Bm + (size_t)b_r * N + n_blk + b_c;

    float acc[4][4][4];
#pragma unroll
    for (int i = 0; i < 4; i++)
#pragma unroll
        for (int j = 0; j < 4; j++)
#pragma unroll
            for (int c = 0; c < 4; c++) acc[i][j][c] = 0.f;

    float4 pa[4], pb[4];
#pragma unroll
    for (int it = 0; it < 4; it++) {
        pa[it] = *(const float4*)(Ag + (size_t)(it * 32) * K);
        pb[it] = *(const float4*)(Bg + (size_t)(it * 8) * N);
    }

    for (int kt = 0; kt < K; kt += BK) {
#pragma unroll
        for (int it = 0; it < 4; it++) {
            float4 v = pa[it];
            float4 w;
            w.x = to_tf32(v.x); w.y = to_tf32(v.y);
            w.z = to_tf32(v.z); w.w = to_tf32(v.w);
            *(float4*)&As[a_r + it * 32][a_c] = w;
            v = pb[it];
            w.x = to_tf32(v.x); w.y = to_tf32(v.y);
            w.z = to_tf32(v.z); w.w = to_tf32(v.w);
            *(float4*)&Bs[b_r + it * 8][b_c] = w;
        }
        __syncthreads();

        if (kt + BK < K) {
#pragma unroll
            for (int it = 0; it < 4; it++) {
                pa[it] = *(const float4*)(Ag + (kt + BK) + (size_t)(it * 32) * K);
                pb[it] = *(const float4*)(Bg + (size_t)(kt + BK + it * 8) * N);
            }
        }

#pragma unroll
        for (int kk = 0; kk < 4; kk++) {
            const int k0 = kk * 8;
            uint32_t af[4][4], bf[4][2];
#pragma unroll
            for (int i = 0; i < 4; i++) {
                const float* ab = &As[wm + i * 16 + g][k0 + t];
                af[i][0] = __float_as_uint(ab[0]);
                af[i][1] = __float_as_uint(ab[8 * A_PAD]);
                af[i][2] = __float_as_uint(ab[4]);
                af[i][3] = __float_as_uint(ab[8 * A_PAD + 4]);
            }
#pragma unroll
            for (int j = 0; j < 4; j++) {
                const float* bb = &Bs[k0 + t][wn + j * 8 + g];
                bf[j][0] = __float_as_uint(bb[0]);
                bf[j][1] = __float_as_uint(bb[4 * B_PAD]);
            }
#pragma unroll
            for (int i = 0; i < 4; i++)
#pragma unroll
                for (int j = 0; j < 4; j++)
                    mma_tf32(acc[i][j], af[i], bf[j]);
        }
        __syncthreads();
    }

#pragma unroll
    for (int i = 0; i < 4; i++) {
#pragma unroll
        for (int j = 0; j < 4; j++) {
            int row = m_blk + wm + i * 16 + g;
            int col = n_blk + wn + j * 8 + t * 2;
            float b0 = 0.f, b1 = 0.f;
            if (hasBias) { b0 = bias[col]; b1 = bias[col + 1]; }
            float2 v0 = make_float2(acc[i][j][0] + b0, acc[i][j][1] + b1);
            float2 v1 = make_float2(acc[i][j][2] + b0, acc[i][j][3] + b1);
            *(float2*)&C[(size_t)row * N + col] = v0;
            *(float2*)&C[(size_t)(row + 8) * N + col] = v1;
        }
    }
}

// ---------------------------------------------------------------------------
// GLM partial RoPE (unchanged)
// ---------------------------------------------------------------------------
__global__ void rope_kernel(float* __restrict__ qkv, const int* __restrict__ positions)
{
    int idx = blockIdx.x * blockDim.x + threadIdx.x;
    const int total = TOKS * (NH_ + NKV_) * (ROT_ / 2);
    if (idx >= total) return;
    int i = idx & 31;
    int head = (idx >> 5) % (NH_ + NKV_);
    int tok = idx / ((NH_ + NKV_) * 32);
    int pos = positions[tok];

    double freq = exp(-((double)(2 * i) / (double)ROT_) * log(10000.0));
    double ang = (double)pos * freq;
    float c = (float)cos(ang);
    float s = (float)sin(ang);

    int off = (head < NH_) ? head * HD_ : (NH_ * HD_ + (head - NH_) * HD_);
    float* p = qkv + (size_t)tok * QKV_N + off + 2 * i;
    float x1 = p[0], x2 = p[1];
    p[0] = x1 * c - x2 * s;
    p[1] = x1 * s + x2 * c;
}

// ---------------------------------------------------------------------------
// TF32 tensor-core causal GQA flash attention.
// CTA: 128 q-rows x (64 k-cols per tile). 8 warps, 16 q-rows each.
// Q fragments held in registers for the whole CTA (64 regs/thread).
// Smem: Ks[d][j] transposed (pad 136), Vs[j][d] natural (pad 136);
//       Q staging [128][132] overlaps Ks/Vs region (used only before loop).
// P (C-layout) -> A-layout via quad-local shuffles; online softmax per row.
// ---------------------------------------------------------------------------
#define AT_BM 128
#define AT_BN 64
#define KT_PAD 136
#define V_PAD  136
#define Q_PAD  132
#define AT_SMEM_FLOATS (128 * KT_PAD + 64 * V_PAD)   // 26112 floats = 104448 B

__global__ __launch_bounds__(256, 1) void attn_tc_kernel(
    const float* __restrict__ qkv, float* __restrict__ out)
{
    extern __shared__ float sm[];
    float* Ks = sm;                       // [128][KT_PAD]  (tile K transposed)
    float* Vs = sm + 128 * KT_PAD;        // [64][V_PAD]
    float* Qs = sm;                       // [128][Q_PAD]   staging (pre-loop only)

    const int qt = blockIdx.x;            // q tile (128 rows)
    const int h  = blockIdx.y;
    const int b  = blockIdx.z;
    const int kvh = h >> 4;               // G = 16
    const int tid = threadIdx.x;
    const int lane = tid & 31;
    const int warp = tid >> 5;
    const int g = lane >> 2;
    const int t = lane & 3;

    const int r0 = warp * 16 + g;         // local q row (and +8)
    const int row0 = qt * AT_BM + r0;
    const int row1 = row0 + 8;

    const float* qbase = qkv + (size_t)(b * S_ + qt * AT_BM) * QKV_N + h * HD_;
    const float* kbase = qkv + (size_t)b * S_ * QKV_N + NH_ * HD_ + kvh * HD_;
    const float* vbase = kbase + NKV_ * HD_;

    // ---- stage Q to smem (tf32-rounded), then extract A-fragments ----
    for (int idx = tid; idx < AT_BM * 32; idx += 256) {
        int row = idx >> 5, c = idx & 31;
        float4 v = *(const float4*)(qbase + (size_t)row * QKV_N + c * 4);
        float4 w;
        w.x = to_tf32(v.x); w.y = to_tf32(v.y);
        w.z = to_tf32(v.z); w.w = to_tf32(v.w);
        *(float4*)&Qs[row * Q_PAD + c * 4] = w;
    }
    __syncthreads();

    uint32_t qf[16][4];
#pragma unroll
    for (int kc = 0; kc < 16; kc++) {
        const float* ab = &Qs[r0 * Q_PAD + kc * 8 + t];
        qf[kc][0] = __float_as_uint(ab[0]);
        qf[kc][1] = __float_as_uint(ab[8 * Q_PAD]);
        qf[kc][2] = __float_as_uint(ab[4]);
        qf[kc][3] = __float_as_uint(ab[8 * Q_PAD + 4]);
    }

    float oacc[16][4];
#pragma unroll
    for (int nc = 0; nc < 16; nc++)
#pragma unroll
        for (int c = 0; c < 4; c++) oacc[nc][c] = 0.f;

    float m0 = -1e30f, m1 = -1e30f, l0 = 0.f, l1 = 0.f;
    const float scale = 0.08838834764831845f;   // 1/sqrt(128)

    const int n_tiles = 2 * qt + 2;

    for (int kt = 0; kt < n_tiles; kt++) {
        const int kb = kt * AT_BN;
        __syncthreads();   // protect Qs (iter 0) / Ks,Vs (prior iter readers)

        // ---- load K^T tile: Ks[d][j] = K[kb+j][d]  (STS conflict-free) ----
        {
            int j = lane + (warp & 1) * 32;          // 0..63
            int dbase = (warp >> 1) * 32;            // 0,32,64,96
            const float* krow = kbase + (size_t)(kb + j) * QKV_N + dbase;
#pragma unroll
            for (int it = 0; it < 8; it++) {
                float4 k4 = *(const float4*)(krow + it * 4);
                int d0 = dbase + it * 4;
                Ks[(d0 + 0) * KT_PAD + j] = to_tf32(k4.x);
                Ks[(d0 + 1) * KT_PAD + j] = to_tf32(k4.y);
                Ks[(d0 + 2) * KT_PAD + j] = to_tf32(k4.z);
                Ks[(d0 + 3) * KT_PAD + j] = to_tf32(k4.w);
            }
            // ---- V natural layout (coalesced) ----
            int c4 = lane * 4;
#pragma unroll
            for (int it = 0; it < 8; it++) {
                int rowv = warp + it * 8;
                float4 v4 = *(const float4*)(vbase + (size_t)(kb + rowv) * QKV_N + c4);
                float4 w4;
                w4.x = to_tf32(v4.x); w4.y = to_tf32(v4.y);
                w4.z = to_tf32(v4.z); w4.w = to_tf32(v4.w);
                *(float4*)&Vs[rowv * V_PAD + c4] = w4;
            }
        }
        __syncthreads();

        // ---- S = Q @ K^T  (16 k-steps over d) ----
        float sacc[8][4];
#pragma unroll
        for (int jc = 0; jc < 8; jc++)
#pragma unroll
            for (int c = 0; c < 4; c++) sacc[jc][c] = 0.f;

#pragma unroll
        for (int kc = 0; kc < 16; kc++) {
            uint32_t bf[8][2];
#pragma unroll
            for (int jc = 0; jc < 8; jc++) {
                bf[jc][0] = __float_as_uint(Ks[(kc * 8 + t) * KT_PAD + jc * 8 + g]);
                bf[jc][1] = __float_as_uint(Ks[(kc * 8 + t + 4) * KT_PAD + jc * 8 + g]);
            }
#pragma unroll
            for (int jc = 0; jc < 8; jc++)
                mma_tf32(sacc[jc], qf[kc], bf[jc]);
        }

        // ---- scale + causal mask + online softmax ----
        const bool msk = (kt >= 2 * qt);
        float mx0 = -1e30f, mx1 = -1e30f;
#pragma unroll
        for (int jc = 0; jc < 8; jc++) {
            int c0 = kb + jc * 8 + 2 * t;
            int c1 = c0 + 1;
            float s0 = sacc[jc][0] * scale;
            float s1 = sacc[jc][1] * scale;
            float s2 = sacc[jc][2] * scale;
            float s3 = sacc[jc][3] * scale;
            if (msk) {
                if (c0 > row0) s0 = -1e30f;
                if (c1 > row0) s1 = -1e30f;
                if (c0 > row1) s2 = -1e30f;
                if (c1 > row1) s3 = -1e30f;
            }
            sacc[jc][0] = s0; sacc[jc][1] = s1;
            sacc[jc][2] = s2; sacc[jc][3] = s3;
            mx0 = fmaxf(mx0, fmaxf(s0, s1));
            mx1 = fmaxf(mx1, fmaxf(s2, s3));
        }
        mx0 = fmaxf(mx0, __shfl_xor_sync(0xffffffffu, mx0, 1));
        mx0 = fmaxf(mx0, __shfl_xor_sync(0xffffffffu, mx0, 2));
        mx1 = fmaxf(mx1, __shfl_xor_sync(0xffffffffu, mx1, 1));
        mx1 = fmaxf(mx1, __shfl_xor_sync(0xffffffffu, mx1, 2));

        float mn0 = fmaxf(m0, mx0), mn1 = fmaxf(m1, mx1);
        float al0 = __expf(m0 - mn0), al1 = __expf(m1 - mn1);
        m0 = mn0; m1 = mn1;

        float lt0 = 0.f, lt1 = 0.f;
#pragma unroll
        for (int jc = 0; jc < 8; jc++) {
            float p0 = __expf(sacc[jc][0] - mn0);
            float p1 = __expf(sacc[jc][1] - mn0);
            float p2 = __expf(sacc[jc][2] - mn1);
            float p3 = __expf(sacc[jc][3] - mn1);
            sacc[jc][0] = p0; sacc[jc][1] = p1;
            sacc[jc][2] = p2; sacc[jc][3] = p3;
            lt0 += p0 + p1;
            lt1 += p2 + p3;
        }
        lt0 += __shfl_xor_sync(0xffffffffu, lt0, 1);
        lt0 += __shfl_xor_sync(0xffffffffu, lt0, 2);
        lt1 += __shfl_xor_sync(0xffffffffu, lt1, 1);
        lt1 += __shfl_xor_sync(0xffffffffu, lt1, 2);
        l0 = l0 * al0 + lt0;
        l1 = l1 * al1 + lt1;

#pragma unroll
        for (int nc = 0; nc < 16; nc++) {
            oacc[nc][0] *= al0; oacc[nc][1] *= al0;
            oacc[nc][2] *= al1; oacc[nc][3] *= al1;
        }

        // ---- O += P @ V  (P C-layout -> A-layout via quad shuffles) ----
        const int src0 = (lane & 28) | (t >> 1);
        const int src1 = src0 | 2;
        const bool odd = (t & 1);
#pragma unroll
        for (int jc = 0; jc < 8; jc++) {
            float p0 = to_tf32(sacc[jc][0]);
            float p1 = to_tf32(sacc[jc][1]);
            float p2 = to_tf32(sacc[jc][2]);
            float p3 = to_tf32(sacc[jc][3]);
            float x00 = __shfl_sync(0xffffffffu, p0, src0);
            float x10 = __shfl_sync(0xffffffffu, p1, src0);
            float x01 = __shfl_sync(0xffffffffu, p0, src1);
            float x11 = __shfl_sync(0xffffffffu, p1, src1);
            float x20 = __shfl_sync(0xffffffffu, p2, src0);
            float x30 = __shfl_sync(0xffffffffu, p3, src0);
            float x21 = __shfl_sync(0xffffffffu, p2, src1);
            float x31 = __shfl_sync(0xffffffffu, p3, src1);
            uint32_t a[4];
            a[0] = __float_as_uint(odd ? x10 : x00);   // (g,    t)
            a[1] = __float_as_uint(odd ? x30 : x20);   // (g+8,  t)
            a[2] = __float_as_uint(odd ? x11 : x01);   // (g,    t+4)
            a[3] = __float_as_uint(odd ? x31 : x21);   // (g+8,  t+4)
#pragma unroll
            for (int nc = 0; nc < 16; nc++) {
                uint32_t bv[2];
                bv[0] = __float_as_uint(Vs[(jc * 8 + t) * V_PAD + nc * 8 + g]);
                bv[1] = __float_as_uint(Vs[(jc * 8 + t + 4) * V_PAD + nc * 8 + g]);
                mma_tf32(oacc[nc], a, bv);
            }
        }
    }

    // ---- epilogue ----
    float il0 = 1.f / l0, il1 = 1.f / l1;
    float* o0 = out + (size_t)(b * S_ + row0) * H_ + h * HD_ + 2 * t;
    float* o1 = out + (size_t)(b * S_ + row1) * H_ + h * HD_ + 2 * t;
#pragma unroll
    for (int nc = 0; nc < 16; nc++) {
        *(float2*)(o0 + nc * 8) = make_float2(oacc[nc][0] * il0, oacc[nc][1] * il0);
        *(float2*)(o1 + nc * 8) = make_float2(oacc[nc][2] * il1, oacc[nc][3] * il1);
    }
}

// ---------------------------------------------------------------------------
extern "C" void kernel_launch(void* const* d_in, const int* in_sizes, int n_in,
                              void* d_out, int out_size)
{
    const float* hidden    = (const float*)d_in[0];
    const float* w_qkv     = (const float*)d_in[1];
    const float* b_qkv     = (const float*)d_in[2];
    const float* w_dense   = (const float*)d_in[3];
    const int*   positions = (const int*)d_in[4];
    float* out = (float*)d_out;

    float* qkv_buf = nullptr;
    float* attn_buf = nullptr;
    cudaGetSymbolAddress((void**)&qkv_buf, g_qkv);
    cudaGetSymbolAddress((void**)&attn_buf, g_attn);

    // 1) QKV GEMM + bias (tf32 tensor cores)
    tf32_gemm_kernel<<<dim3(QKV_N / BN, TOKS / BM), 256>>>(
        hidden, w_qkv, b_qkv, qkv_buf, TOKS, QKV_N, H_, 1);

    // 2) RoPE in place on q + k heads
    {
        int total = TOKS * (NH_ + NKV_) * (ROT_ / 2);
        rope_kernel<<<(total + 255) / 256, 256>>>(qkv_buf, positions);
    }

    // 3) causal GQA flash attention (tf32 tensor cores)
    {
        size_t smem = (size_t)AT_SMEM_FLOATS * sizeof(float);   // 104448 B
        cudaFuncSetAttribute(attn_tc_kernel, cudaFuncAttributeMaxDynamicSharedMemorySize, (int)smem);
        attn_tc_kernel<<<dim3(S_ / AT_BM, NH_, B_), 256, smem>>>(qkv_buf, attn_buf);
    }

    // 4) dense GEMM (tf32 tensor cores)
    tf32_gemm_kernel<<<dim3(H_ / BN, TOKS / BM), 256>>>(
        attn_buf, w_dense, nullptr, out, TOKS, H_, H_, 0);
}